// round 12
// baseline (speedup 1.0000x reference)
#include <cuda_runtime.h>
#include <cstdint>

// SoftBCELoss, round 12: bulk-async smem pipeline, halo folded into the copy.
// input/target: [B, C=2, T=60000] fp32; out: 3 scalars (total, beat, down).
// target_process == circular 7-tap conv {1.328125,.65625,.3125,.125} + min(.,1)
// loss_ch = 0.5 * sum(bce) / (B*T).  BCE in log2 domain, *ln2 at the end.
//
// 2048 blocks, each owns a quarter row (3750 float4) = 15 tiles of 256
// float4 through a 4-stage cp.async.bulk + mbarrier pipeline. The tgt copy
// is extended by 1 float4 on each side so the conv halo arrives in the same
// bulk transfer; only the two circular row-wrap edges (quarter 0 left, and
// quarter 3 right) are patched from registers preloaded at block start.

#define NTHR   256
#define T4     15000
#define CHUNK4 3750
#define TILE4  256
#define NTILES 15
#define LAST4  (CHUNK4 - (NTILES - 1) * TILE4)   // 166
#define NSTAGE 4

__device__ float2       g_block[2048];
__device__ unsigned int g_count = 0;

struct Stage {
    float4 inp[TILE4];
    float4 tgt[TILE4 + 2];   // [0]=left halo, [1..n]=payload, [n+1]=right halo
};

__device__ __forceinline__ unsigned s2u(const void* p) {
    return (unsigned)__cvta_generic_to_shared(p);
}
__device__ __forceinline__ void mbar_init(unsigned a, unsigned cnt) {
    asm volatile("mbarrier.init.shared.b64 [%0], %1;" :: "r"(a), "r"(cnt) : "memory");
}
__device__ __forceinline__ void mbar_expect(unsigned a, unsigned bytes) {
    asm volatile("mbarrier.arrive.expect_tx.shared.b64 _, [%0], %1;"
                 :: "r"(a), "r"(bytes) : "memory");
}
__device__ __forceinline__ void mbar_wait(unsigned a, unsigned phase) {
    asm volatile(
        "{\n\t.reg .pred P;\n\t"
        "WL_%=:\n\t"
        "mbarrier.try_wait.parity.acquire.cta.shared::cta.b64 P, [%0], %1, 0x989680;\n\t"
        "@P bra.uni WD_%=;\n\t"
        "bra.uni WL_%=;\n\t"
        "WD_%=:\n\t}"
        :: "r"(a), "r"(phase) : "memory");
}
__device__ __forceinline__ void bulk_g2s(unsigned dst, const void* src,
                                         unsigned bytes, unsigned mbar) {
    asm volatile(
        "cp.async.bulk.shared::cluster.global.mbarrier::complete_tx::bytes "
        "[%0], [%1], %2, [%3];"
        :: "r"(dst), "l"(src), "r"(bytes), "r"(mbar) : "memory");
}

__global__ __launch_bounds__(NTHR)
void loss_pipe12(const float4* __restrict__ d_inp,
                 const float4* __restrict__ d_tgt,
                 float* __restrict__ out,
                 int n_chunks)
{
    __shared__ Stage    st[NSTAGE];
    __shared__ uint64_t mbar[NSTAGE];
    __shared__ float    swarp[NTHR / 32];
    __shared__ double   sa[NTHR], sb[NTHR];

    const float W0 = 1.328125f, W1 = 0.65625f, W2 = 0.3125f, W3 = 0.125f;

    const int tid  = threadIdx.x;
    const int bid  = blockIdx.x;
    const int row  = bid >> 2;
    const int q    = bid & 3;
    const int base = row * T4;
    const int cs   = q * CHUNK4;
    const bool leftWrap  = (cs == 0);   // tile 0 left halo wraps to T4-1
    const bool rightWrap = (q == 3);    // last tile right halo wraps to 0

    if (tid == 0) {
        #pragma unroll
        for (int s = 0; s < NSTAGE; s++) mbar_init(s2u(&mbar[s]), 1);
    }
    __syncthreads();

    // preload the (rare) circular-wrap halo values; overlaps with first TMAs
    float4 wrapL = make_float4(0,0,0,0), wrapR = make_float4(0,0,0,0);
    if (tid == 0) {
        if (leftWrap)  wrapL = d_tgt[base + T4 - 1];
        if (rightWrap) wrapR = d_tgt[base];

        // initial 4 stage fills
        #pragma unroll
        for (int k = 0; k < NSTAGE; k++) {
            const int n   = (k == NTILES - 1) ? LAST4 : TILE4;
            const int lok = (k == 0 && leftWrap) ? 0 : 1;
            const int rok = (k == NTILES - 1 && rightWrap) ? 0 : 1;
            const unsigned mb = s2u(&mbar[k]);
            mbar_expect(mb, (unsigned)((n + n + lok + rok) * 16));
            bulk_g2s(s2u(&st[k].inp[0]),
                     d_inp + base + cs + k * TILE4, n * 16, mb);
            bulk_g2s(s2u(&st[k].tgt[1 - lok]),
                     d_tgt + base + cs + k * TILE4 - lok,
                     (n + lok + rok) * 16, mb);
        }
    }

    float acc = 0.0f;   // log2-domain partial

    for (int k = 0; k < NTILES; k++) {
        const int s   = k & (NSTAGE - 1);
        const int n_k = (k == NTILES - 1) ? LAST4 : TILE4;

        mbar_wait(s2u(&mbar[s]), (k >> 2) & 1);

        // patch circular-wrap halos (rare: only edge tiles of edge blocks)
        if (tid == 0) {
            if (k == 0 && leftWrap)               st[s].tgt[0]       = wrapL;
            if (k == NTILES - 1 && rightWrap)     st[s].tgt[n_k + 1] = wrapR;
        }
        __syncthreads();

        if (tid < n_k) {
            const float4 m4 = st[s].tgt[tid];        // payload idx tid-1 / halo
            const float4 c4 = st[s].tgt[tid + 1];
            const float4 q4 = st[s].tgt[tid + 2];
            const float4 p4 = st[s].inp[tid];

            const float w0 = m4.y, w1 = m4.z, w2 = m4.w;
            const float w3 = c4.x, w4 = c4.y, w5 = c4.z, w6 = c4.w;
            const float w7 = q4.x, w8 = q4.y, w9 = q4.z;

            float tv[4];
            tv[0] = fminf(W0*w3 + W1*(w2+w4) + W2*(w1+w5) + W3*(w0+w6), 1.0f);
            tv[1] = fminf(W0*w4 + W1*(w3+w5) + W2*(w2+w6) + W3*(w1+w7), 1.0f);
            tv[2] = fminf(W0*w5 + W1*(w4+w6) + W2*(w3+w7) + W3*(w2+w8), 1.0f);
            tv[3] = fminf(W0*w6 + W1*(w5+w7) + W2*(w4+w8) + W3*(w3+w9), 1.0f);

            const float pv[4] = {p4.x, p4.y, p4.z, p4.w};
            #pragma unroll
            for (int i = 0; i < 4; i++) {
                const float p   = pv[i];
                const float lg0 = __log2f(1.0f - p);   // bare MUFU.LG2
                const float lg1 = __log2f(p);
                acc += lg0 + tv[i] * (lg1 - lg0);       // bce = -ln2 * this
            }
        }
        __syncthreads();   // all reads of stage s complete

        // refill stage s with tile k+NSTAGE
        if (tid == 0 && k + NSTAGE < NTILES) {
            const int kk  = k + NSTAGE;
            const int n   = (kk == NTILES - 1) ? LAST4 : TILE4;
            const int lok = 1;  // kk >= 4, never the row start
            const int rok = (kk == NTILES - 1 && rightWrap) ? 0 : 1;
            const unsigned mb = s2u(&mbar[s]);
            mbar_expect(mb, (unsigned)((n + n + lok + rok) * 16));
            bulk_g2s(s2u(&st[s].inp[0]),
                     d_inp + base + cs + kk * TILE4, n * 16, mb);
            bulk_g2s(s2u(&st[s].tgt[0]),
                     d_tgt + base + cs + kk * TILE4 - 1,
                     (n + 1 + rok) * 16, mb);
        }
    }

    // ---- block reduce (log2 units) ----
    #pragma unroll
    for (int o = 16; o > 0; o >>= 1)
        acc += __shfl_xor_sync(0xffffffffu, acc, o);
    const int lane = tid & 31, wid = tid >> 5;
    if (lane == 0) swarp[wid] = acc;
    __syncthreads();

    __shared__ bool s_last;
    if (tid == 0) {
        float a = 0.0f;
        #pragma unroll
        for (int i = 0; i < NTHR / 32; i++) a += swarp[i];
        float2 v = (row & 1) ? make_float2(0.0f, a) : make_float2(a, 0.0f);
        g_block[bid] = v;
        __threadfence();
        unsigned t = atomicInc(&g_count, (unsigned)(n_chunks - 1));
        s_last = (t == (unsigned)(n_chunks - 1));
    }
    __syncthreads();
    if (!s_last) return;

    // ---- last block: deterministic finalize ----
    double a = 0.0, b = 0.0;
    for (int i = tid; i < n_chunks; i += NTHR) {
        float2 v = g_block[i];
        a += (double)v.x;
        b += (double)v.y;
    }
    sa[tid] = a;
    sb[tid] = b;
    __syncthreads();
    for (int o = NTHR / 2; o > 0; o >>= 1) {
        if (tid < o) { sa[tid] += sa[tid + o]; sb[tid] += sb[tid + o]; }
        __syncthreads();
    }
    if (tid == 0) {
        const double LN2 = 0.6931471805599453;
        const double dn  = (double)n_chunks * (double)(CHUNK4 * 4) * 0.5;  // B*T
        float tb = (float)(-0.5 * LN2 * sa[0] / dn);
        float td = (float)(-0.5 * LN2 * sb[0] / dn);
        out[0] = tb + td;
        out[1] = tb;
        out[2] = td;
    }
}

extern "C" void kernel_launch(void* const* d_in, const int* in_sizes, int n_in,
                              void* d_out, int out_size)
{
    const float4* inp = (const float4*)d_in[0];
    const float4* tgt = (const float4*)d_in[1];
    const int n        = in_sizes[0];            // B*C*T
    const int n_chunks = n / (4 * CHUNK4);       // 2048 for B=256
    loss_pipe12<<<n_chunks, NTHR>>>(inp, tgt, (float*)d_out, n_chunks);
}

// round 14
// speedup vs baseline: 1.0046x; 1.0046x over previous
#include <cuda_runtime.h>
#include <cstdint>

// SoftBCELoss, round 14: warp-specialized TMA producer + consumer warps.
// (R13 with the 288-thread finalize-reduction bug fixed: only threads 0..255
//  participate in the last-block sum; R13 dropped sa[257..287] -> rel_err
//  0.106 == 31/288.)
//
// input/target: [B, C=2, T=60000] fp32; out: 3 scalars (total, beat, down).
// target_process == circular 7-tap conv {1.328125,.65625,.3125,.125} + min(.,1)
// loss_ch = 0.5 * sum(bce) / (B*T).  BCE in log2 domain, *ln2 at the end.
//
// 2048 blocks x 288 threads. Warps 0-7 consume tiles (256 float4 payload,
// 1 float4/lane); warp 8's lane 0 is an autonomous producer that refills a
// stage the moment its empty barrier fires -- NO __syncthreads in the loop.
// Halo (incl circular row wrap) arrives as two extra 16B bulk copies.

#define NTHR   288
#define NCONS  256
#define T4     15000
#define CHUNK4 3750
#define TILE4  256
#define NTILES 15
#define LAST4  (CHUNK4 - (NTILES - 1) * TILE4)   // 166
#define NSTAGE 4

__device__ float2       g_block[2048];
__device__ unsigned int g_count = 0;

struct Stage {
    float4 inp[TILE4];
    float4 tgt[TILE4 + 2];   // [0]=left halo, [1..n]=payload, [n+1]=right halo
};

__device__ __forceinline__ unsigned s2u(const void* p) {
    return (unsigned)__cvta_generic_to_shared(p);
}
__device__ __forceinline__ void mbar_init(unsigned a, unsigned cnt) {
    asm volatile("mbarrier.init.shared.b64 [%0], %1;" :: "r"(a), "r"(cnt) : "memory");
}
__device__ __forceinline__ void mbar_expect(unsigned a, unsigned bytes) {
    asm volatile("mbarrier.arrive.expect_tx.shared.b64 _, [%0], %1;"
                 :: "r"(a), "r"(bytes) : "memory");
}
__device__ __forceinline__ void mbar_arrive(unsigned a) {
    asm volatile("mbarrier.arrive.shared.b64 _, [%0];" :: "r"(a) : "memory");
}
__device__ __forceinline__ void mbar_wait(unsigned a, unsigned phase) {
    asm volatile(
        "{\n\t.reg .pred P;\n\t"
        "WL_%=:\n\t"
        "mbarrier.try_wait.parity.acquire.cta.shared::cta.b64 P, [%0], %1, 0x989680;\n\t"
        "@P bra.uni WD_%=;\n\t"
        "bra.uni WL_%=;\n\t"
        "WD_%=:\n\t}"
        :: "r"(a), "r"(phase) : "memory");
}
__device__ __forceinline__ void bulk_g2s(unsigned dst, const void* src,
                                         unsigned bytes, unsigned mbar) {
    asm volatile(
        "cp.async.bulk.shared::cluster.global.mbarrier::complete_tx::bytes "
        "[%0], [%1], %2, [%3];"
        :: "r"(dst), "l"(src), "r"(bytes), "r"(mbar) : "memory");
}

__global__ __launch_bounds__(NTHR)
void loss_ws14(const float4* __restrict__ d_inp,
               const float4* __restrict__ d_tgt,
               float* __restrict__ out,
               int n_chunks)
{
    __shared__ Stage    st[NSTAGE];
    __shared__ uint64_t mb_full[NSTAGE], mb_empty[NSTAGE];
    __shared__ float    swarp[NTHR / 32];
    __shared__ double   sa[NCONS], sb[NCONS];

    const float W0 = 1.328125f, W1 = 0.65625f, W2 = 0.3125f, W3 = 0.125f;

    const int tid  = threadIdx.x;
    const int wrp  = tid >> 5;
    const int bid  = blockIdx.x;
    const int row  = bid >> 2;
    const int q    = bid & 3;
    const int base = row * T4;
    const int cs   = q * CHUNK4;

    if (tid == 0) {
        #pragma unroll
        for (int s = 0; s < NSTAGE; s++) {
            mbar_init(s2u(&mb_full[s]),  1);       // producer's expect_tx arrives
            mbar_init(s2u(&mb_empty[s]), NCONS);   // all consumer threads arrive
        }
    }
    __syncthreads();

    float acc = 0.0f;   // log2-domain partial

    if (wrp == 8) {
        // ---------------- producer: warp 8, lane 0 ----------------
        if ((tid & 31) == 0) {
            #pragma unroll 1
            for (int k = 0; k < NTILES; k++) {
                const int s = k & (NSTAGE - 1);
                if (k >= NSTAGE)
                    mbar_wait(s2u(&mb_empty[s]), ((k >> 2) - 1) & 1);

                const int n  = (k == NTILES - 1) ? LAST4 : TILE4;
                const int g0 = cs + k * TILE4;
                const int gl = (g0 == 0)      ? (T4 - 1) : (g0 - 1);
                const int gr = (g0 + n == T4) ? 0        : (g0 + n);
                const unsigned mb = s2u(&mb_full[s]);
                mbar_expect(mb, (unsigned)((2 * n + 2) * 16));
                bulk_g2s(s2u(&st[s].inp[0]),    d_inp + base + g0, n * 16, mb);
                bulk_g2s(s2u(&st[s].tgt[1]),    d_tgt + base + g0, n * 16, mb);
                bulk_g2s(s2u(&st[s].tgt[0]),    d_tgt + base + gl, 16,     mb);
                bulk_g2s(s2u(&st[s].tgt[n+1]),  d_tgt + base + gr, 16,     mb);
            }
        }
    } else {
        // ---------------- consumers: warps 0-7 ----------------
        #pragma unroll 1
        for (int k = 0; k < NTILES; k++) {
            const int s   = k & (NSTAGE - 1);
            const int n_k = (k == NTILES - 1) ? LAST4 : TILE4;

            mbar_wait(s2u(&mb_full[s]), (k >> 2) & 1);

            if (tid < n_k) {
                const float4 m4 = st[s].tgt[tid];
                const float4 c4 = st[s].tgt[tid + 1];
                const float4 q4 = st[s].tgt[tid + 2];
                const float4 p4 = st[s].inp[tid];

                const float w0 = m4.y, w1 = m4.z, w2 = m4.w;
                const float w3 = c4.x, w4 = c4.y, w5 = c4.z, w6 = c4.w;
                const float w7 = q4.x, w8 = q4.y, w9 = q4.z;

                float tv[4];
                tv[0] = fminf(W0*w3 + W1*(w2+w4) + W2*(w1+w5) + W3*(w0+w6), 1.0f);
                tv[1] = fminf(W0*w4 + W1*(w3+w5) + W2*(w2+w6) + W3*(w1+w7), 1.0f);
                tv[2] = fminf(W0*w5 + W1*(w4+w6) + W2*(w3+w7) + W3*(w2+w8), 1.0f);
                tv[3] = fminf(W0*w6 + W1*(w5+w7) + W2*(w4+w8) + W3*(w3+w9), 1.0f);

                const float pv[4] = {p4.x, p4.y, p4.z, p4.w};
                #pragma unroll
                for (int i = 0; i < 4; i++) {
                    const float p   = pv[i];
                    const float lg0 = __log2f(1.0f - p);   // bare MUFU.LG2
                    const float lg1 = __log2f(p);
                    acc += lg0 + tv[i] * (lg1 - lg0);       // bce = -ln2 * this
                }
            }
            mbar_arrive(s2u(&mb_empty[s]));   // every consumer thread
        }
    }

    __syncthreads();   // join producer + consumers before reduction

    // ---- block reduce (log2 units); producer warp contributes acc=0 ----
    #pragma unroll
    for (int o = 16; o > 0; o >>= 1)
        acc += __shfl_xor_sync(0xffffffffu, acc, o);
    const int lane = tid & 31;
    if (lane == 0) swarp[wrp] = acc;
    __syncthreads();

    __shared__ bool s_last;
    if (tid == 0) {
        float a = 0.0f;
        #pragma unroll
        for (int i = 0; i < NTHR / 32; i++) a += swarp[i];
        float2 v = (row & 1) ? make_float2(0.0f, a) : make_float2(a, 0.0f);
        g_block[bid] = v;
        __threadfence();
        unsigned t = atomicInc(&g_count, (unsigned)(n_chunks - 1));
        s_last = (t == (unsigned)(n_chunks - 1));
    }
    __syncthreads();
    if (!s_last) return;

    // ---- last block: deterministic finalize (threads 0..255 only) ----
    if (tid < NCONS) {
        double a = 0.0, b = 0.0;
        for (int i = tid; i < n_chunks; i += NCONS) {
            float2 v = g_block[i];
            a += (double)v.x;
            b += (double)v.y;
        }
        sa[tid] = a;
        sb[tid] = b;
    }
    __syncthreads();
    for (int o = NCONS / 2; o > 0; o >>= 1) {
        if (tid < o) { sa[tid] += sa[tid + o]; sb[tid] += sb[tid + o]; }
        __syncthreads();
    }
    if (tid == 0) {
        const double LN2 = 0.6931471805599453;
        const double dn  = (double)n_chunks * (double)(CHUNK4 * 4) * 0.5;  // B*T
        float tb = (float)(-0.5 * LN2 * sa[0] / dn);
        float td = (float)(-0.5 * LN2 * sb[0] / dn);
        out[0] = tb + td;
        out[1] = tb;
        out[2] = td;
    }
}

extern "C" void kernel_launch(void* const* d_in, const int* in_sizes, int n_in,
                              void* d_out, int out_size)
{
    const float4* inp = (const float4*)d_in[0];
    const float4* tgt = (const float4*)d_in[1];
    const int n        = in_sizes[0];            // B*C*T
    const int n_chunks = n / (4 * CHUNK4);       // 2048 for B=256
    loss_ws14<<<n_chunks, NTHR>>>(inp, tgt, (float*)d_out, n_chunks);
}